// round 5
// baseline (speedup 1.0000x reference)
#include <cuda_runtime.h>
#include <cuda_bf16.h>

// S4D Vandermonde kernel:
//   K[d,l] = dt[d] * Re( sum_n  C[d,n]*B[d,n] * exp( (A_real+i*A_imag)[d,n]*dt[d] * l ) )
// D_MODEL=1024, N_STATE=64, L=1024.
//
// Strategy: one block per d, one thread per state n. Complex geometric
// recurrence z_{l+1} = z_l * r (4 FMA-pipe ops) replaces per-term exp/sincos
// (MUFU-bound). Exact reseed via expf/sincosf every 64-step tile bounds
// numerical drift. Per-tile 64x64 smem transpose turns the cross-n reduction
// into conflict-free float4 row sums.

#define D_MODEL  1024
#define N_STATE  64
#define SEQ_LEN  1024
#define TILE     64
#define ROW_PITCH 68   // words; 68*4=272B => 16B-aligned rows, conflict-free

__global__ void __launch_bounds__(N_STATE) s4d_kernel(
    const float* __restrict__ A_real,
    const float* __restrict__ A_imag,
    const float* __restrict__ C,
    const float* __restrict__ log_dt,
    const float* __restrict__ B,
    float* __restrict__ out)
{
    __shared__ float tilebuf[TILE * ROW_PITCH];   // 64*68*4 = 17408 B

    const int d = blockIdx.x;
    const int n = threadIdx.x;

    const float dt = expf(log_dt[d]);

    const int idx = d * N_STATE + n;
    const float cr = C[idx * 2 + 0];
    const float ci = C[idx * 2 + 1];
    const float Bn = B[idx];

    // Fold B and the final dt scale into the coefficient.
    const float coef_r = cr * Bn * dt;
    const float coef_i = ci * Bn * dt;

    const float a = A_real[idx] * dt;   // decay rate per step
    const float b = A_imag[idx] * dt;   // phase per step

    // Per-step multiplier r = exp(a) * (cos b + i sin b)
    float sb, cb;
    sincosf(b, &sb, &cb);
    const float e1 = expf(a);
    const float rr = e1 * cb;
    const float ri = e1 * sb;

    float* outrow = out + (size_t)d * SEQ_LEN;

    #pragma unroll 1
    for (int t = 0; t < SEQ_LEN / TILE; ++t) {
        // Exact reseed at tile start: z = exp(a*l0) * (cos(b*l0) + i sin(b*l0))
        const float l0 = (float)(t * TILE);
        const float mag = expf(a * l0);
        float sp, cp;
        sincosf(b * l0, &sp, &cp);
        float zr = mag * cp;
        float zi = mag * sp;

        // March 64 steps; contribution for each l goes to smem row j, col n.
        #pragma unroll
        for (int j = 0; j < TILE; ++j) {
            tilebuf[j * ROW_PITCH + n] = fmaf(coef_r, zr, -(coef_i * zi));
            const float nzr = fmaf(zr, rr, -(zi * ri));
            const float nzi = fmaf(zr, ri, zi * rr);
            zr = nzr;
            zi = nzi;
        }
        __syncthreads();

        // Thread n sums row n (l = t*TILE + n) across all 64 states.
        const float4* rp =
            reinterpret_cast<const float4*>(&tilebuf[n * ROW_PITCH]);
        float s0 = 0.f, s1 = 0.f, s2 = 0.f, s3 = 0.f;
        #pragma unroll
        for (int k = 0; k < TILE / 4; ++k) {
            const float4 v = rp[k];
            s0 += v.x; s1 += v.y; s2 += v.z; s3 += v.w;
        }
        outrow[t * TILE + n] = (s0 + s1) + (s2 + s3);
        __syncthreads();   // tilebuf reused next tile
    }
}

extern "C" void kernel_launch(void* const* d_in, const int* in_sizes, int n_in,
                              void* d_out, int out_size)
{
    const float* A_real = (const float*)d_in[0];
    const float* A_imag = (const float*)d_in[1];
    const float* C      = (const float*)d_in[2];
    const float* log_dt = (const float*)d_in[3];
    const float* B      = (const float*)d_in[4];
    float* out = (float*)d_out;

    s4d_kernel<<<D_MODEL, N_STATE>>>(A_real, A_imag, C, log_dt, B, out);
}

// round 6
// speedup vs baseline: 1.9762x; 1.9762x over previous
#include <cuda_runtime.h>
#include <cuda_bf16.h>

// S4D Vandermonde kernel:
//   K[d,l] = dt[d] * Re( sum_n  C[d,n]*B[d,n] * exp((A_real+i*A_imag)[d,n]*dt[d]*l) )
// D_MODEL=1024, N_STATE=64, L=1024.
//
// R5 strategy:
//  - Second-order real recurrence x_{l+1} = p*x_l + q*x_{l-1} (p=2e^a cos b,
//    q=-e^{2a}) replaces the complex geometric recurrence: 2 FMA-ops/state/step.
//  - Packed f32x2 math (mul/fma/add .f32x2, PTX-only) advances 2 states per
//    instruction; 4 states per thread => 16 threads per d.
//  - States are pre-summed in registers before the smem transpose: tile traffic
//    drops 4x (4KB write + 4KB read per 64-l tile).
//  - 2 d per warp (16 lanes each), sub-warp tiles, __syncwarp only.
//  - Seeds advance tile-to-tile by exact complex multiply with r^64 (one
//    expf/sincosf per thread, no per-tile MUFU).

#define D_MODEL  1024
#define N_STATE  64
#define SEQ_LEN  1024
#define TILE     64
#define NSPLIT   4
#define L_PER    (SEQ_LEN / NSPLIT)   // 256
#define TILES_PER (L_PER / TILE)      // 4
#define PITCH    36                   // words: 36 % 32 == 4 -> conflict-free

typedef unsigned long long u64;

__device__ __forceinline__ u64 pk(float lo, float hi) {
    u64 r;
    asm("mov.b64 %0, {%1, %2};" : "=l"(r)
        : "r"(__float_as_uint(lo)), "r"(__float_as_uint(hi)));
    return r;
}
__device__ __forceinline__ float hsum(u64 v) {
    unsigned int a, b;
    asm("mov.b64 {%0, %1}, %2;" : "=r"(a), "=r"(b) : "l"(v));
    return __uint_as_float(a) + __uint_as_float(b);
}
__device__ __forceinline__ u64 f2mul(u64 a, u64 b) {
    u64 d; asm("mul.rn.f32x2 %0, %1, %2;" : "=l"(d) : "l"(a), "l"(b)); return d;
}
__device__ __forceinline__ u64 f2fma(u64 a, u64 b, u64 c) {
    u64 d; asm("fma.rn.f32x2 %0, %1, %2, %3;" : "=l"(d) : "l"(a), "l"(b), "l"(c)); return d;
}
__device__ __forceinline__ u64 f2add(u64 a, u64 b) {
    u64 d; asm("add.rn.f32x2 %0, %1, %2;" : "=l"(d) : "l"(a), "l"(b)); return d;
}

__global__ void __launch_bounds__(64) s4d_kernel(
    const float* __restrict__ A_real,
    const float* __restrict__ A_imag,
    const float* __restrict__ C,
    const float* __restrict__ log_dt,
    const float* __restrict__ B,
    float* __restrict__ out)
{
    // One 64x36-word tile per warp (two d's interleaved in 32 columns).
    __shared__ __align__(16) float tilebuf[2][TILE * PITCH];

    const int lane = threadIdx.x & 31;
    const int warp = threadIdx.x >> 5;
    const int q    = lane & 15;      // lane within the d-group
    const int dsel = lane >> 4;      // which of the warp's two d's
    const int d    = blockIdx.x * 4 + warp * 2 + dsel;
    const int lbase = blockIdx.y * L_PER;

    const float dt = expf(log_dt[d]);

    // Per-state scalar setup (4 states: n = q + 16*i).
    float p_[4], qv_[4], rr_[4], nri_[4], ur_[4], ui_[4], gr_[4], gi_[4];
    #pragma unroll
    for (int i = 0; i < 4; ++i) {
        const int n   = q + 16 * i;
        const int idx = d * N_STATE + n;
        const float a  = A_real[idx] * dt;   // per-step log-magnitude
        const float b  = A_imag[idx] * dt;   // per-step phase
        const float Bn = B[idx];
        const float coefr = C[2 * idx + 0] * Bn * dt;
        const float coefi = C[2 * idx + 1] * Bn * dt;

        float sb, cb; sincosf(b, &sb, &cb);
        const float e1 = expf(a);
        const float rr = e1 * cb;            // Re(r)
        const float ri = e1 * sb;            // Im(r)
        p_[i]   = 2.0f * rr;                 // recurrence: x' = p*x + q*x_prev
        qv_[i]  = -(e1 * e1);
        rr_[i]  = rr;
        nri_[i] = -ri;

        // Seed u = coef * exp(a*l0) * cis(b*l0) at this block's l-base.
        const float l0 = (float)lbase;
        const float m  = expf(a * l0);
        float sl, cl; sincosf(b * l0, &sl, &cl);
        ur_[i] = m * (coefr * cl - coefi * sl);
        ui_[i] = m * (coefr * sl + coefi * cl);

        // Tile-advance multiplier g = r^64 (computed exactly).
        const float m64 = expf(a * 64.0f);
        float s64, c64; sincosf(b * 64.0f, &s64, &c64);
        gr_[i] = m64 * c64;
        gi_[i] = m64 * s64;
    }

    // Pack state pairs: A = (n=q, n=q+16), B = (n=q+32, n=q+48).
    const u64 p2A  = pk(p_[0], p_[1]),    p2B  = pk(p_[2], p_[3]);
    const u64 q2A  = pk(qv_[0], qv_[1]),  q2B  = pk(qv_[2], qv_[3]);
    const u64 rr2A = pk(rr_[0], rr_[1]),  rr2B = pk(rr_[2], rr_[3]);
    const u64 nri2A = pk(nri_[0], nri_[1]), nri2B = pk(nri_[2], nri_[3]);
    const u64 gRA  = pk(gr_[0], gr_[1]),  gRB  = pk(gr_[2], gr_[3]);
    const u64 gIA  = pk(gi_[0], gi_[1]),  gIB  = pk(gi_[2], gi_[3]);
    const u64 ngIA = pk(-gi_[0], -gi_[1]), ngIB = pk(-gi_[2], -gi_[3]);
    u64 uRA = pk(ur_[0], ur_[1]), uRB = pk(ur_[2], ur_[3]);
    u64 uIA = pk(ui_[0], ui_[1]), uIB = pk(ui_[2], ui_[3]);

    float* tw = tilebuf[warp];
    float* outd = out + (size_t)d * SEQ_LEN + lbase;

    #pragma unroll 1
    for (int t = 0; t < TILES_PER; ++t) {
        // Seeds: x0 = Re(u), x1 = Re(u*r).
        u64 xmA = uRA, xmB = uRB;
        u64 xcA = f2fma(uIA, nri2A, f2mul(uRA, rr2A));
        u64 xcB = f2fma(uIB, nri2B, f2mul(uRB, rr2B));
        tw[0 * PITCH + lane] = hsum(f2add(xmA, xmB));
        tw[1 * PITCH + lane] = hsum(f2add(xcA, xcB));

        // 62 more steps; only the FMA2 is on the dependency chain (4 cyc/step).
        #pragma unroll
        for (int j = 2; j < TILE; ++j) {
            const u64 xnA = f2fma(p2A, xcA, f2mul(q2A, xmA));
            const u64 xnB = f2fma(p2B, xcB, f2mul(q2B, xmB));
            xmA = xcA; xcA = xnA;
            xmB = xcB; xcB = xnB;
            tw[j * PITCH + lane] = hsum(f2add(xnA, xnB));
        }

        // Advance seeds: u <- u * r^64 (complex, packed).
        {
            const u64 nuRA = f2fma(uIA, ngIA, f2mul(uRA, gRA));
            const u64 nuIA = f2fma(uIA, gRA,  f2mul(uRA, gIA));
            const u64 nuRB = f2fma(uIB, ngIB, f2mul(uRB, gRB));
            const u64 nuIB = f2fma(uIB, gRB,  f2mul(uRB, gIB));
            uRA = nuRA; uIA = nuIA; uRB = nuRB; uIB = nuIB;
        }
        __syncwarp();

        // Reduction: lane handles 4 rows of its own d's 16-column half.
        #pragma unroll
        for (int k = 0; k < 4; ++k) {
            const int row = q + 16 * k;
            const ulonglong2* bp = reinterpret_cast<const ulonglong2*>(
                &tw[row * PITCH + dsel * 16]);
            const ulonglong2 v0 = bp[0], v1 = bp[1], v2 = bp[2], v3 = bp[3];
            const u64 s01 = f2add(v0.x, v0.y);
            const u64 s23 = f2add(v1.x, v1.y);
            const u64 s45 = f2add(v2.x, v2.y);
            const u64 s67 = f2add(v3.x, v3.y);
            const u64 sT  = f2add(f2add(s01, s23), f2add(s45, s67));
            outd[t * TILE + row] = hsum(sT);
        }
        __syncwarp();   // tile reused next iteration
    }
}

extern "C" void kernel_launch(void* const* d_in, const int* in_sizes, int n_in,
                              void* d_out, int out_size)
{
    const float* A_real = (const float*)d_in[0];
    const float* A_imag = (const float*)d_in[1];
    const float* C      = (const float*)d_in[2];
    const float* log_dt = (const float*)d_in[3];
    const float* B      = (const float*)d_in[4];
    float* out = (float*)d_out;

    dim3 grid(D_MODEL / 4, NSPLIT);
    s4d_kernel<<<grid, 64>>>(A_real, A_imag, C, log_dt, B, out);
}